// round 12
// baseline (speedup 1.0000x reference)
#include <cuda_runtime.h>
#include <cuda_fp16.h>
#include <math.h>
#include <stdint.h>

// Problem constants
#define BB   8
#define TT   1024
#define DM   1024
#define NH   16
#define HS   64
#define MM   (BB*TT)          // 8192 rows
#define DFF  (4*DM)           // 4096

// ---------------- scratch (device globals; no allocation allowed) ------------
__device__ __half g_h  [MM*DM];                 // LN outputs (fp16)
__device__ __half g_q  [MM*DM];
__device__ __half g_k  [MM*DM];
__device__ __half g_v  [MM*DM];
__device__ __half g_att[MM*DM];                 // attention output (fp16)
__device__ float  g_x1 [MM*DM];
__device__ __half g_mid[(size_t)MM*DFF];        // MLP mid (fp16)
// fp16 weight copies (layout unchanged: [K,N] row-major)
__device__ __half g_hwq[DM*DM];
__device__ __half g_hwk[DM*DM];
__device__ __half g_hwv[DM*DM];
__device__ __half g_hwo[DM*DM];
__device__ __half g_hw1[(size_t)DM*DFF];
__device__ __half g_hw2[(size_t)DFF*DM];

// ---------------- helpers ----------------------------------------------------
__device__ __forceinline__ uint32_t smem_u32(const void* p) {
    uint32_t a;
    asm("{ .reg .u64 t; cvta.to.shared.u64 t, %1; cvt.u32.u64 %0, t; }" : "=r"(a) : "l"(p));
    return a;
}
__device__ __forceinline__ void cp16(uint32_t dst, const void* src) {
    asm volatile("cp.async.cg.shared.global [%0], [%1], 16;" :: "r"(dst), "l"(src));
}
__device__ __forceinline__ void cp_commit() {
    asm volatile("cp.async.commit_group;" ::: "memory");
}
template<int N>
__device__ __forceinline__ void cp_wait() {
    asm volatile("cp.async.wait_group %0;" :: "n"(N) : "memory");
}
__device__ __forceinline__ void ldsm_x4(uint32_t* r, uint32_t addr) {
    asm volatile("ldmatrix.sync.aligned.m8n8.x4.shared.b16 {%0,%1,%2,%3}, [%4];"
        : "=r"(r[0]), "=r"(r[1]), "=r"(r[2]), "=r"(r[3]) : "r"(addr));
}
__device__ __forceinline__ void ldsm_x4_t(uint32_t* r, uint32_t addr) {
    asm volatile("ldmatrix.sync.aligned.m8n8.x4.trans.shared.b16 {%0,%1,%2,%3}, [%4];"
        : "=r"(r[0]), "=r"(r[1]), "=r"(r[2]), "=r"(r[3]) : "r"(addr));
}
__device__ __forceinline__ void mma_f16(float* d, const uint32_t* a, const uint32_t* b) {
    asm volatile(
        "mma.sync.aligned.m16n8k16.row.col.f32.f16.f16.f32 "
        "{%0,%1,%2,%3}, {%4,%5,%6,%7}, {%8,%9}, {%0,%1,%2,%3};"
        : "+f"(d[0]), "+f"(d[1]), "+f"(d[2]), "+f"(d[3])
        : "r"(a[0]), "r"(a[1]), "r"(a[2]), "r"(a[3]), "r"(b[0]), "r"(b[1]));
}

// GEMM smem geometry (bytes). K-chunk = 64 halves. 4-stage pipeline.
#define AS_STRIDE_B 144
#define BS_STRIDE_B 528
#define A_STAGE_B   (128 * AS_STRIDE_B)
#define B_STAGE_B   (64  * BS_STRIDE_B)
#define STAGE_B     (A_STAGE_B + B_STAGE_B)     // 52224
#define SM_BYTES    (4 * STAGE_B)               // 208896

// ---------------- LayerNorm (fp32 in -> fp16 out) ----------------------------
__global__ __launch_bounds__(256) void ln_kernel(
    const float* __restrict__ x, const float* __restrict__ g,
    const float* __restrict__ b, __half* __restrict__ out)
{
    const int row = blockIdx.x;
    const int tid = threadIdx.x;
    const float4* xr = (const float4*)(x + (size_t)row * DM);
    float4 v = xr[tid];
    float s  = v.x + v.y + v.z + v.w;
    float sq = v.x*v.x + v.y*v.y + v.z*v.z + v.w*v.w;
    #pragma unroll
    for (int off = 16; off; off >>= 1) {
        s  += __shfl_xor_sync(0xffffffffu, s,  off);
        sq += __shfl_xor_sync(0xffffffffu, sq, off);
    }
    __shared__ float ss[8], ssq[8];
    const int w = tid >> 5, lane = tid & 31;
    if (lane == 0) { ss[w] = s; ssq[w] = sq; }
    __syncthreads();
    float tot = 0.f, totq = 0.f;
    #pragma unroll
    for (int i = 0; i < 8; i++) { tot += ss[i]; totq += ssq[i]; }
    const float mean = tot * (1.f / DM);
    const float var  = totq * (1.f / DM) - mean * mean;
    const float inv  = rsqrtf(var + 1e-5f);
    float4 gg = ((const float4*)g)[tid];
    float4 bb = ((const float4*)b)[tid];
    __half2* orow = (__half2*)(out + (size_t)row * DM);
    orow[tid*2]   = __floats2half2_rn((v.x-mean)*inv*gg.x + bb.x, (v.y-mean)*inv*gg.y + bb.y);
    orow[tid*2+1] = __floats2half2_rn((v.z-mean)*inv*gg.z + bb.z, (v.w-mean)*inv*gg.w + bb.w);
}

// ---------------- all weights fp32 -> fp16, one launch -----------------------
// segments (in float4 units): Wq,Wk,Wv,Wo = 262144 each; W1,W2 = 1048576 each
#define N4D 262144
#define N4F 1048576
#define N4TOT (4*N4D + 2*N4F)   // 3145728
__global__ __launch_bounds__(256) void cvt_all_kernel(
    const float* __restrict__ Wq, const float* __restrict__ Wk,
    const float* __restrict__ Wv, const float* __restrict__ Wo,
    const float* __restrict__ W1, const float* __restrict__ W2,
    __half* __restrict__ hwq, __half* __restrict__ hwk,
    __half* __restrict__ hwv, __half* __restrict__ hwo,
    __half* __restrict__ hw1, __half* __restrict__ hw2)
{
    int i = blockIdx.x * 256 + threadIdx.x;
    if (i >= N4TOT) return;
    const float* src; __half* dst; int off;
    if      (i < 1*N4D)          { src = Wq; dst = hwq; off = i; }
    else if (i < 2*N4D)          { src = Wk; dst = hwk; off = i - 1*N4D; }
    else if (i < 3*N4D)          { src = Wv; dst = hwv; off = i - 2*N4D; }
    else if (i < 4*N4D)          { src = Wo; dst = hwo; off = i - 3*N4D; }
    else if (i < 4*N4D + N4F)    { src = W1; dst = hw1; off = i - 4*N4D; }
    else                         { src = W2; dst = hw2; off = i - 4*N4D - N4F; }
    float4 v = ((const float4*)src)[off];
    ((__half2*)dst)[2*off]   = __floats2half2_rn(v.x, v.y);
    ((__half2*)dst)[2*off+1] = __floats2half2_rn(v.z, v.w);
}

// ---------------- fp16 tensor GEMM, 128x256 tile, K-chunk 64, 4-stage --------
// MODE 0: plain, fp16 out (z selects among 3 weight/output pairs)
// MODE 1: +bias +residual(fp32), fp32 out
// MODE 2: +bias, relu, fp16 out
template<int MODE>
__global__ __launch_bounds__(256) void tgemm_kernel(
    const __half* __restrict__ A,
    const __half* __restrict__ W0, const __half* __restrict__ W1w, const __half* __restrict__ W2w,
    const float* __restrict__ bias, const float* __restrict__ R,
    void* C0v, void* C1v, void* C2v,
    int K, int Nw)
{
    extern __shared__ __align__(128) char smc[];
    const uint32_t smBase = smem_u32(smc);

    const int tid  = threadIdx.x;
    const int wid  = tid >> 5, lane = tid & 31;
    const int warpM = wid >> 2, warpN = wid & 3;
    const int z = blockIdx.z;
    const __half* Wp = (z == 0) ? W0 : (z == 1) ? W1w : W2w;
    void* Cv = (z == 0) ? C0v : (z == 1) ? C1v : C2v;

    const int mBase = blockIdx.y * 128;
    const int nBase = blockIdx.x * 256;
    const __half* Aptr = A  + (size_t)mBase * K;
    const __half* Bptr = Wp + nBase;

    float acc[4][8][4];
    #pragma unroll
    for (int i = 0; i < 4; i++)
        #pragma unroll
        for (int j = 0; j < 8; j++)
            #pragma unroll
            for (int t = 0; t < 4; t++) acc[i][j][t] = 0.f;

    auto FILL = [&](int c) {
        const int k0 = c * 64;
        const uint32_t aB = smBase + (uint32_t)((c & 3) * STAGE_B);
        const uint32_t bB = aB + A_STAGE_B;
        #pragma unroll
        for (int i = 0; i < 4; i++) {
            const int idx = i * 256 + tid;
            const int r = idx >> 3, cc = idx & 7;
            cp16(aB + (uint32_t)(r * AS_STRIDE_B + cc * 16),
                 Aptr + (size_t)r * K + k0 + cc * 8);
        }
        #pragma unroll
        for (int i = 0; i < 8; i++) {
            const int idx = i * 256 + tid;
            const int r = idx >> 5, cc = idx & 31;
            cp16(bB + (uint32_t)(r * BS_STRIDE_B + cc * 16),
                 Bptr + (size_t)(k0 + r) * Nw + cc * 8);
        }
        cp_commit();
    };

    auto COMPUTE = [&](int buf) {
        const uint32_t aB = smBase + (uint32_t)(buf * STAGE_B);
        const uint32_t bB = aB + A_STAGE_B;
        const int lr  = (lane & 7) + ((lane >> 3) & 1) * 8;
        const int lc8 = (lane >> 4) * 8;
        #pragma unroll
        for (int kk = 0; kk < 4; kk++) {
            uint32_t af[4][4], bf[8][2];
            #pragma unroll
            for (int mi = 0; mi < 4; mi++) {
                const int row = warpM * 64 + mi * 16 + lr;
                ldsm_x4(af[mi], aB + (uint32_t)(row * AS_STRIDE_B + (kk * 16 + lc8) * 2));
            }
            #pragma unroll
            for (int np = 0; np < 4; np++) {
                uint32_t r4[4];
                const int krow = kk * 16 + lr;
                const int col  = warpN * 64 + np * 16 + lc8;
                ldsm_x4_t(r4, bB + (uint32_t)(krow * BS_STRIDE_B + col * 2));
                bf[np*2][0]   = r4[0]; bf[np*2][1]   = r4[1];
                bf[np*2+1][0] = r4[2]; bf[np*2+1][1] = r4[3];
            }
            #pragma unroll
            for (int mi = 0; mi < 4; mi++)
                #pragma unroll
                for (int ni = 0; ni < 8; ni++)
                    mma_f16(acc[mi][ni], af[mi], bf[ni]);
        }
    };

    const int nch = K / 64;
    FILL(0);
    FILL(1);
    FILL(2);
    for (int c = 0; c < nch; c++) {
        if (c + 2 < nch)      cp_wait<2>();
        else if (c + 1 < nch) cp_wait<1>();
        else                  cp_wait<0>();
        __syncthreads();
        if (c + 3 < nch) FILL(c + 3);
        COMPUTE(c & 3);
        __syncthreads();
    }

    #pragma unroll
    for (int mi = 0; mi < 4; mi++) {
        #pragma unroll
        for (int ni = 0; ni < 8; ni++) {
            const int gr = mBase + warpM * 64 + mi * 16 + (lane >> 2);
            const int gc = nBase + warpN * 64 + ni * 8 + (lane & 3) * 2;
            float v0 = acc[mi][ni][0], v1 = acc[mi][ni][1];
            float v2 = acc[mi][ni][2], v3 = acc[mi][ni][3];
            if (MODE != 0) {
                const float b0 = bias[gc], b1 = bias[gc + 1];
                v0 += b0; v1 += b1; v2 += b0; v3 += b1;
            }
            if (MODE == 1) {
                const float* r0p = R + (size_t)gr * Nw + gc;
                const float* r1p = R + (size_t)(gr + 8) * Nw + gc;
                v0 += r0p[0]; v1 += r0p[1]; v2 += r1p[0]; v3 += r1p[1];
            }
            if constexpr (MODE != 1) {
                __half* C = (__half*)Cv;
                if (MODE == 2) {
                    v0 = fmaxf(v0, 0.f); v1 = fmaxf(v1, 0.f);
                    v2 = fmaxf(v2, 0.f); v3 = fmaxf(v3, 0.f);
                }
                *(__half2*)(C + (size_t)gr * Nw + gc)       = __floats2half2_rn(v0, v1);
                *(__half2*)(C + (size_t)(gr + 8) * Nw + gc) = __floats2half2_rn(v2, v3);
            } else {
                float* C = (float*)Cv;
                *(float2*)(C + (size_t)gr * Nw + gc)       = make_float2(v0, v1);
                *(float2*)(C + (size_t)(gr + 8) * Nw + gc) = make_float2(v2, v3);
            }
        }
    }
}

// ---------------- Tensor-core flash attention (causal, scale 1/32) -----------
// 256 query rows / block, 8 warps (32 rows each); KV tiles of 64, 3-stage.
#define KS_STRIDE 144                 // bytes per row (64 halves + 8 pad)
#define Q_SMEM_B  (256 * KS_STRIDE)   // 36864
#define KV_TILE_B (64 * KS_STRIDE)    // 9216
#define ATT_SMEM  (Q_SMEM_B + 6 * KV_TILE_B)   // 92160

__global__ __launch_bounds__(256) void attn_kernel(
    const __half* __restrict__ Q, const __half* __restrict__ K,
    const __half* __restrict__ V, __half* __restrict__ O)
{
    extern __shared__ __align__(128) char smc[];
    const uint32_t smBase = smem_u32(smc);

    const int tid = threadIdx.x;
    const int wid = tid >> 5, lane = tid & 31;
    const int qt = blockIdx.x, hh = blockIdx.y, bb = blockIdx.z;
    const int qb = qt * 256;
    const size_t base = (size_t)bb * TT * DM + (size_t)hh * HS;

    const int lr  = (lane & 7) + ((lane >> 3) & 1) * 8;
    const int lc8 = (lane >> 4) * 8;

    // ---- fill Q (256 rows); committed with KV tile 0 as group 0 ----
    #pragma unroll
    for (int i = 0; i < 8; i++) {
        const int idx = i * 256 + tid;
        const int r = idx >> 3, c = idx & 7;
        cp16(smBase + (uint32_t)(r * KS_STRIDE + c * 16),
             Q + base + (size_t)(qb + r) * DM + c * 8);
    }
    auto FILLKV = [&](int kt) {
        const int s = kt % 3;
        const uint32_t kB = smBase + Q_SMEM_B + (uint32_t)(s * KV_TILE_B);
        const uint32_t vB = smBase + Q_SMEM_B + (uint32_t)((3 + s) * KV_TILE_B);
        #pragma unroll
        for (int i = 0; i < 2; i++) {
            const int idx = i * 256 + tid;
            const int r = idx >> 3, c = idx & 7;
            const size_t g = base + (size_t)(kt * 64 + r) * DM + c * 8;
            cp16(kB + (uint32_t)(r * KS_STRIDE + c * 16), K + g);
            cp16(vB + (uint32_t)(r * KS_STRIDE + c * 16), V + g);
        }
        cp_commit();
    };
    const int ntiles = 4 * qt + 4;
    FILLKV(0);              // group 0: Q + KV0
    FILLKV(1);              // group 1
    FILLKV(2);              // group 2

    uint32_t qa[2][4][4];
    float oacc[2][8][4];
    float mrow[2][2], lrow[2][2];
    #pragma unroll
    for (int mi = 0; mi < 2; mi++) {
        mrow[mi][0] = mrow[mi][1] = -1e30f;
        lrow[mi][0] = lrow[mi][1] = 0.f;
        #pragma unroll
        for (int ni = 0; ni < 8; ni++)
            #pragma unroll
            for (int t = 0; t < 4; t++) oacc[mi][ni][t] = 0.f;
    }

    for (int kt = 0; kt < ntiles; kt++) {
        if (kt + 2 < ntiles)      cp_wait<2>();
        else if (kt + 1 < ntiles) cp_wait<1>();
        else                      cp_wait<0>();
        __syncthreads();
        if (kt == 0) {
            #pragma unroll
            for (int mi = 0; mi < 2; mi++)
                #pragma unroll
                for (int kk = 0; kk < 4; kk++) {
                    const int row = wid * 32 + mi * 16 + lr;
                    ldsm_x4(qa[mi][kk],
                            smBase + (uint32_t)(row * KS_STRIDE + (kk * 16 + lc8) * 2));
                }
        }
        const int s = kt % 3;
        const uint32_t kB = smBase + Q_SMEM_B + (uint32_t)(s * KV_TILE_B);
        const uint32_t vB = smBase + Q_SMEM_B + (uint32_t)((3 + s) * KV_TILE_B);

        // ---- S = Q @ K^T ----
        float sacc[2][8][4];
        #pragma unroll
        for (int mi = 0; mi < 2; mi++)
            #pragma unroll
            for (int ni = 0; ni < 8; ni++)
                #pragma unroll
                for (int t = 0; t < 4; t++) sacc[mi][ni][t] = 0.f;
        #pragma unroll
        for (int kk = 0; kk < 4; kk++) {
            uint32_t kb[8][2];
            #pragma unroll
            for (int ng = 0; ng < 4; ng++) {
                uint32_t r4[4];
                ldsm_x4(r4, kB + (uint32_t)((ng * 16 + lr) * KS_STRIDE + (kk * 16 + lc8) * 2));
                kb[ng*2][0]   = r4[0]; kb[ng*2][1]   = r4[2];
                kb[ng*2+1][0] = r4[1]; kb[ng*2+1][1] = r4[3];
            }
            #pragma unroll
            for (int mi = 0; mi < 2; mi++)
                #pragma unroll
                for (int ni = 0; ni < 8; ni++)
                    mma_f16(sacc[mi][ni], qa[mi][kk], kb[ni]);
        }

        // ---- online softmax in fragments ----
        const bool doMask = (kt >= 4 * qt);
        uint32_t pa[2][4][4];
        #pragma unroll
        for (int mi = 0; mi < 2; mi++) {
            const int row0 = qb + wid * 32 + mi * 16 + (lane >> 2);
            const int row1 = row0 + 8;
            float mx0 = -1e30f, mx1 = -1e30f;
            #pragma unroll
            for (int ni = 0; ni < 8; ni++) {
                const int c0 = kt * 64 + ni * 8 + (lane & 3) * 2;
                float s0 = sacc[mi][ni][0] * 0.03125f;
                float s1 = sacc[mi][ni][1] * 0.03125f;
                float s2 = sacc[mi][ni][2] * 0.03125f;
                float s3 = sacc[mi][ni][3] * 0.03125f;
                if (doMask) {
                    if (c0     > row0) s0 = -1e30f;
                    if (c0 + 1 > row0) s1 = -1e30f;
                    if (c0     > row1) s2 = -1e30f;
                    if (c0 + 1 > row1) s3 = -1e30f;
                }
                sacc[mi][ni][0] = s0; sacc[mi][ni][1] = s1;
                sacc[mi][ni][2] = s2; sacc[mi][ni][3] = s3;
                mx0 = fmaxf(mx0, fmaxf(s0, s1));
                mx1 = fmaxf(mx1, fmaxf(s2, s3));
            }
            #pragma unroll
            for (int off = 1; off <= 2; off <<= 1) {
                mx0 = fmaxf(mx0, __shfl_xor_sync(0xffffffffu, mx0, off));
                mx1 = fmaxf(mx1, __shfl_xor_sync(0xffffffffu, mx1, off));
            }
            const float mn0 = fmaxf(mrow[mi][0], mx0);
            const float mn1 = fmaxf(mrow[mi][1], mx1);
            const float cor0 = __expf(mrow[mi][0] - mn0);
            const float cor1 = __expf(mrow[mi][1] - mn1);
            mrow[mi][0] = mn0; mrow[mi][1] = mn1;
            float sum0 = 0.f, sum1 = 0.f;
            float p[8][4];
            #pragma unroll
            for (int ni = 0; ni < 8; ni++) {
                p[ni][0] = __expf(sacc[mi][ni][0] - mn0);
                p[ni][1] = __expf(sacc[mi][ni][1] - mn0);
                p[ni][2] = __expf(sacc[mi][ni][2] - mn1);
                p[ni][3] = __expf(sacc[mi][ni][3] - mn1);
                sum0 += p[ni][0] + p[ni][1];
                sum1 += p[ni][2] + p[ni][3];
            }
            lrow[mi][0] = lrow[mi][0] * cor0 + sum0;
            lrow[mi][1] = lrow[mi][1] * cor1 + sum1;
            #pragma unroll
            for (int ni = 0; ni < 8; ni++) {
                oacc[mi][ni][0] *= cor0; oacc[mi][ni][1] *= cor0;
                oacc[mi][ni][2] *= cor1; oacc[mi][ni][3] *= cor1;
            }
            #pragma unroll
            for (int jk = 0; jk < 4; jk++) {
                __half2 h0 = __floats2half2_rn(p[2*jk][0],   p[2*jk][1]);
                __half2 h1 = __floats2half2_rn(p[2*jk][2],   p[2*jk][3]);
                __half2 h2 = __floats2half2_rn(p[2*jk+1][0], p[2*jk+1][1]);
                __half2 h3 = __floats2half2_rn(p[2*jk+1][2], p[2*jk+1][3]);
                pa[mi][jk][0] = *(uint32_t*)&h0;
                pa[mi][jk][1] = *(uint32_t*)&h1;
                pa[mi][jk][2] = *(uint32_t*)&h2;
                pa[mi][jk][3] = *(uint32_t*)&h3;
            }
        }

        // ---- O += P @ V ----
        #pragma unroll
        for (int jk = 0; jk < 4; jk++) {
            uint32_t vb[8][2];
            #pragma unroll
            for (int ng = 0; ng < 4; ng++) {
                uint32_t r4[4];
                ldsm_x4_t(r4, vB + (uint32_t)((jk * 16 + lr) * KS_STRIDE + (ng * 16 + lc8) * 2));
                vb[ng*2][0]   = r4[0]; vb[ng*2][1]   = r4[1];
                vb[ng*2+1][0] = r4[2]; vb[ng*2+1][1] = r4[3];
            }
            #pragma unroll
            for (int mi = 0; mi < 2; mi++)
                #pragma unroll
                for (int ni = 0; ni < 8; ni++)
                    mma_f16(oacc[mi][ni], pa[mi][jk], vb[ni]);
        }

        __syncthreads();
        if (kt + 3 < ntiles) FILLKV(kt + 3);
    }

    // ---- epilogue: normalize and store fp16 ----
    #pragma unroll
    for (int mi = 0; mi < 2; mi++) {
        float l0 = lrow[mi][0], l1 = lrow[mi][1];
        #pragma unroll
        for (int off = 1; off <= 2; off <<= 1) {
            l0 += __shfl_xor_sync(0xffffffffu, l0, off);
            l1 += __shfl_xor_sync(0xffffffffu, l1, off);
        }
        const float inv0 = 1.f / l0, inv1 = 1.f / l1;
        const int gr0 = qb + wid * 32 + mi * 16 + (lane >> 2);
        #pragma unroll
        for (int ni = 0; ni < 8; ni++) {
            const int gc = ni * 8 + (lane & 3) * 2;
            *(__half2*)(O + base + (size_t)gr0 * DM + gc) =
                __floats2half2_rn(oacc[mi][ni][0] * inv0, oacc[mi][ni][1] * inv0);
            *(__half2*)(O + base + (size_t)(gr0 + 8) * DM + gc) =
                __floats2half2_rn(oacc[mi][ni][2] * inv1, oacc[mi][ni][3] * inv1);
        }
    }
}

// ---------------- launch ----------------------------------------------------
extern "C" void kernel_launch(void* const* d_in, const int* in_sizes, int n_in,
                              void* d_out, int out_size)
{
    const float* x    = (const float*)d_in[0];
    const float* Wq   = (const float*)d_in[1];
    const float* Wk   = (const float*)d_in[2];
    const float* Wv   = (const float*)d_in[3];
    const float* Wo   = (const float*)d_in[4];
    const float* bo   = (const float*)d_in[5];
    const float* W1   = (const float*)d_in[6];
    const float* b1   = (const float*)d_in[7];
    const float* W2   = (const float*)d_in[8];
    const float* b2   = (const float*)d_in[9];
    const float* ln1g = (const float*)d_in[10];
    const float* ln1b = (const float*)d_in[11];
    const float* ln2g = (const float*)d_in[12];
    const float* ln2b = (const float*)d_in[13];
    float* out = (float*)d_out;

    __half *h, *q, *k, *v, *att, *mid, *hwq, *hwk, *hwv, *hwo, *hw1, *hw2;
    float *x1;
    cudaGetSymbolAddress((void**)&h,   g_h);
    cudaGetSymbolAddress((void**)&q,   g_q);
    cudaGetSymbolAddress((void**)&k,   g_k);
    cudaGetSymbolAddress((void**)&v,   g_v);
    cudaGetSymbolAddress((void**)&att, g_att);
    cudaGetSymbolAddress((void**)&x1,  g_x1);
    cudaGetSymbolAddress((void**)&mid, g_mid);
    cudaGetSymbolAddress((void**)&hwq, g_hwq);
    cudaGetSymbolAddress((void**)&hwk, g_hwk);
    cudaGetSymbolAddress((void**)&hwv, g_hwv);
    cudaGetSymbolAddress((void**)&hwo, g_hwo);
    cudaGetSymbolAddress((void**)&hw1, g_hw1);
    cudaGetSymbolAddress((void**)&hw2, g_hw2);

    cudaFuncSetAttribute(tgemm_kernel<0>, cudaFuncAttributeMaxDynamicSharedMemorySize, SM_BYTES);
    cudaFuncSetAttribute(tgemm_kernel<1>, cudaFuncAttributeMaxDynamicSharedMemorySize, SM_BYTES);
    cudaFuncSetAttribute(tgemm_kernel<2>, cudaFuncAttributeMaxDynamicSharedMemorySize, SM_BYTES);
    cudaFuncSetAttribute(attn_kernel,     cudaFuncAttributeMaxDynamicSharedMemorySize, ATT_SMEM);

    // 0) convert all weights to fp16 in one launch
    cvt_all_kernel<<<(N4TOT + 255) / 256, 256>>>(Wq, Wk, Wv, Wo, W1, W2,
                                                 hwq, hwk, hwv, hwo, hw1, hw2);

    // 1) LN1 -> fp16
    ln_kernel<<<MM, 256>>>(x, ln1g, ln1b, h);

    // 2) fused Q,K,V projections -> fp16
    dim3 gqkv(DM / 256, MM / 128, 3);
    tgemm_kernel<0><<<gqkv, 256, SM_BYTES>>>(h, hwq, hwk, hwv, nullptr, nullptr,
                                             q, k, v, DM, DM);

    // 3) tensor-core causal flash attention -> fp16
    dim3 ga(TT / 256, NH, BB);
    attn_kernel<<<ga, 256, ATT_SMEM>>>(q, k, v, att);

    // 4) x1 = x + att @ Wo + bo  (fp32 out)
    dim3 g1(DM / 256, MM / 128, 1);
    tgemm_kernel<1><<<g1, 256, SM_BYTES>>>(att, hwo, hwo, hwo, bo, x,
                                           x1, x1, x1, DM, DM);

    // 5) LN2 -> fp16
    ln_kernel<<<MM, 256>>>(x1, ln2g, ln2b, h);

    // 6) mid = relu(h @ W1 + b1) -> fp16
    dim3 g2(DFF / 256, MM / 128, 1);
    tgemm_kernel<2><<<g2, 256, SM_BYTES>>>(h, hw1, hw1, hw1, b1, nullptr,
                                           mid, mid, mid, DM, DFF);

    // 7) out = x1 + mid @ W2 + b2  (fp32 out)
    tgemm_kernel<1><<<g1, 256, SM_BYTES>>>(mid, hw2, hw2, hw2, b2, x1,
                                           out, out, out, DFF, DM);
}

// round 15
// speedup vs baseline: 1.0284x; 1.0284x over previous
#include <cuda_runtime.h>
#include <cuda_fp16.h>
#include <math.h>
#include <stdint.h>

// Problem constants
#define BB   8
#define TT   1024
#define DM   1024
#define NH   16
#define HS   64
#define MM   (BB*TT)          // 8192 rows
#define DFF  (4*DM)           // 4096

// ---------------- scratch (device globals; no allocation allowed) ------------
__device__ __half g_h  [MM*DM];                 // LN outputs (fp16)
__device__ __half g_q  [MM*DM];
__device__ __half g_k  [MM*DM];
__device__ __half g_v  [MM*DM];
__device__ __half g_att[MM*DM];                 // attention output (fp16)
__device__ float  g_x1 [MM*DM];
__device__ __half g_mid[(size_t)MM*DFF];        // MLP mid (fp16)
// fp16 weight copies (layout unchanged: [K,N] row-major)
__device__ __half g_hwq[DM*DM];
__device__ __half g_hwk[DM*DM];
__device__ __half g_hwv[DM*DM];
__device__ __half g_hwo[DM*DM];
__device__ __half g_hw1[(size_t)DM*DFF];
__device__ __half g_hw2[(size_t)DFF*DM];

// ---------------- helpers ----------------------------------------------------
__device__ __forceinline__ uint32_t smem_u32(const void* p) {
    uint32_t a;
    asm("{ .reg .u64 t; cvta.to.shared.u64 t, %1; cvt.u32.u64 %0, t; }" : "=r"(a) : "l"(p));
    return a;
}
__device__ __forceinline__ void cp16(uint32_t dst, const void* src) {
    asm volatile("cp.async.cg.shared.global [%0], [%1], 16;" :: "r"(dst), "l"(src));
}
__device__ __forceinline__ void cp_commit() {
    asm volatile("cp.async.commit_group;" ::: "memory");
}
template<int N>
__device__ __forceinline__ void cp_wait() {
    asm volatile("cp.async.wait_group %0;" :: "n"(N) : "memory");
}
__device__ __forceinline__ void ldsm_x4(uint32_t* r, uint32_t addr) {
    asm volatile("ldmatrix.sync.aligned.m8n8.x4.shared.b16 {%0,%1,%2,%3}, [%4];"
        : "=r"(r[0]), "=r"(r[1]), "=r"(r[2]), "=r"(r[3]) : "r"(addr));
}
__device__ __forceinline__ void ldsm_x4_t(uint32_t* r, uint32_t addr) {
    asm volatile("ldmatrix.sync.aligned.m8n8.x4.trans.shared.b16 {%0,%1,%2,%3}, [%4];"
        : "=r"(r[0]), "=r"(r[1]), "=r"(r[2]), "=r"(r[3]) : "r"(addr));
}
__device__ __forceinline__ void mma_f16(float* d, const uint32_t* a, const uint32_t* b) {
    asm volatile(
        "mma.sync.aligned.m16n8k16.row.col.f32.f16.f16.f32 "
        "{%0,%1,%2,%3}, {%4,%5,%6,%7}, {%8,%9}, {%0,%1,%2,%3};"
        : "+f"(d[0]), "+f"(d[1]), "+f"(d[2]), "+f"(d[3])
        : "r"(a[0]), "r"(a[1]), "r"(a[2]), "r"(a[3]), "r"(b[0]), "r"(b[1]));
}

// GEMM smem geometry (bytes). K-chunk = 64 halves. 3-stage pipeline.
#define AS_STRIDE_B 144
#define BS_STRIDE_B 528
#define A_STAGE_B   (128 * AS_STRIDE_B)
#define B_STAGE_B   (64  * BS_STRIDE_B)
#define STAGE_B     (A_STAGE_B + B_STAGE_B)     // 52224
#define SM_BYTES    (3 * STAGE_B)               // 156672

// ---------------- LayerNorm (fp32 in -> fp16 out) ----------------------------
__global__ __launch_bounds__(256) void ln_kernel(
    const float* __restrict__ x, const float* __restrict__ g,
    const float* __restrict__ b, __half* __restrict__ out)
{
    const int row = blockIdx.x;
    const int tid = threadIdx.x;
    const float4* xr = (const float4*)(x + (size_t)row * DM);
    float4 v = xr[tid];
    float s  = v.x + v.y + v.z + v.w;
    float sq = v.x*v.x + v.y*v.y + v.z*v.z + v.w*v.w;
    #pragma unroll
    for (int off = 16; off; off >>= 1) {
        s  += __shfl_xor_sync(0xffffffffu, s,  off);
        sq += __shfl_xor_sync(0xffffffffu, sq, off);
    }
    __shared__ float ss[8], ssq[8];
    const int w = tid >> 5, lane = tid & 31;
    if (lane == 0) { ss[w] = s; ssq[w] = sq; }
    __syncthreads();
    float tot = 0.f, totq = 0.f;
    #pragma unroll
    for (int i = 0; i < 8; i++) { tot += ss[i]; totq += ssq[i]; }
    const float mean = tot * (1.f / DM);
    const float var  = totq * (1.f / DM) - mean * mean;
    const float inv  = rsqrtf(var + 1e-5f);
    float4 gg = ((const float4*)g)[tid];
    float4 bb = ((const float4*)b)[tid];
    __half2* orow = (__half2*)(out + (size_t)row * DM);
    orow[tid*2]   = __floats2half2_rn((v.x-mean)*inv*gg.x + bb.x, (v.y-mean)*inv*gg.y + bb.y);
    orow[tid*2+1] = __floats2half2_rn((v.z-mean)*inv*gg.z + bb.z, (v.w-mean)*inv*gg.w + bb.w);
}

// ---------------- all weights fp32 -> fp16, one launch -----------------------
#define N4D 262144
#define N4F 1048576
#define N4TOT (4*N4D + 2*N4F)   // 3145728
__global__ __launch_bounds__(256) void cvt_all_kernel(
    const float* __restrict__ Wq, const float* __restrict__ Wk,
    const float* __restrict__ Wv, const float* __restrict__ Wo,
    const float* __restrict__ W1, const float* __restrict__ W2,
    __half* __restrict__ hwq, __half* __restrict__ hwk,
    __half* __restrict__ hwv, __half* __restrict__ hwo,
    __half* __restrict__ hw1, __half* __restrict__ hw2)
{
    int i = blockIdx.x * 256 + threadIdx.x;
    if (i >= N4TOT) return;
    const float* src; __half* dst; int off;
    if      (i < 1*N4D)          { src = Wq; dst = hwq; off = i; }
    else if (i < 2*N4D)          { src = Wk; dst = hwk; off = i - 1*N4D; }
    else if (i < 3*N4D)          { src = Wv; dst = hwv; off = i - 2*N4D; }
    else if (i < 4*N4D)          { src = Wo; dst = hwo; off = i - 3*N4D; }
    else if (i < 4*N4D + N4F)    { src = W1; dst = hw1; off = i - 4*N4D; }
    else                         { src = W2; dst = hw2; off = i - 4*N4D - N4F; }
    float4 v = ((const float4*)src)[off];
    ((__half2*)dst)[2*off]   = __floats2half2_rn(v.x, v.y);
    ((__half2*)dst)[2*off+1] = __floats2half2_rn(v.z, v.w);
}

// ---------------- fp16 tensor GEMM, 128x256 tile, K-chunk 64, 3-stage --------
// single __syncthreads per mainloop iteration (3-buffer ring makes the
// trailing barrier redundant: FILL(c+2) targets buffer (c-1)%3 whose readers
// are already past the top barrier).
// MODE 0: plain, fp16 out (z selects among 3 weight/output pairs)
// MODE 1: +bias +residual(fp32), fp32 out
// MODE 2: +bias, relu, fp16 out
template<int MODE>
__global__ __launch_bounds__(256) void tgemm_kernel(
    const __half* __restrict__ A,
    const __half* __restrict__ W0, const __half* __restrict__ W1w, const __half* __restrict__ W2w,
    const float* __restrict__ bias, const float* __restrict__ R,
    void* C0v, void* C1v, void* C2v,
    int K, int Nw)
{
    extern __shared__ __align__(128) char smc[];
    const uint32_t smBase = smem_u32(smc);

    const int tid  = threadIdx.x;
    const int wid  = tid >> 5, lane = tid & 31;
    const int warpM = wid >> 2, warpN = wid & 3;
    const int z = blockIdx.z;
    const __half* Wp = (z == 0) ? W0 : (z == 1) ? W1w : W2w;
    void* Cv = (z == 0) ? C0v : (z == 1) ? C1v : C2v;

    const int mBase = blockIdx.y * 128;
    const int nBase = blockIdx.x * 256;
    const __half* Aptr = A  + (size_t)mBase * K;
    const __half* Bptr = Wp + nBase;

    float acc[4][8][4];
    #pragma unroll
    for (int i = 0; i < 4; i++)
        #pragma unroll
        for (int j = 0; j < 8; j++)
            #pragma unroll
            for (int t = 0; t < 4; t++) acc[i][j][t] = 0.f;

    auto FILL = [&](int c) {
        const int k0 = c * 64;
        const uint32_t aB = smBase + (uint32_t)((c % 3) * STAGE_B);
        const uint32_t bB = aB + A_STAGE_B;
        #pragma unroll
        for (int i = 0; i < 4; i++) {
            const int idx = i * 256 + tid;
            const int r = idx >> 3, cc = idx & 7;
            cp16(aB + (uint32_t)(r * AS_STRIDE_B + cc * 16),
                 Aptr + (size_t)r * K + k0 + cc * 8);
        }
        #pragma unroll
        for (int i = 0; i < 8; i++) {
            const int idx = i * 256 + tid;
            const int r = idx >> 5, cc = idx & 31;
            cp16(bB + (uint32_t)(r * BS_STRIDE_B + cc * 16),
                 Bptr + (size_t)(k0 + r) * Nw + cc * 8);
        }
        cp_commit();
    };

    auto COMPUTE = [&](int buf) {
        const uint32_t aB = smBase + (uint32_t)(buf * STAGE_B);
        const uint32_t bB = aB + A_STAGE_B;
        const int lr  = (lane & 7) + ((lane >> 3) & 1) * 8;
        const int lc8 = (lane >> 4) * 8;
        #pragma unroll
        for (int kk = 0; kk < 4; kk++) {
            uint32_t af[4][4], bf[8][2];
            #pragma unroll
            for (int mi = 0; mi < 4; mi++) {
                const int row = warpM * 64 + mi * 16 + lr;
                ldsm_x4(af[mi], aB + (uint32_t)(row * AS_STRIDE_B + (kk * 16 + lc8) * 2));
            }
            #pragma unroll
            for (int np = 0; np < 4; np++) {
                uint32_t r4[4];
                const int krow = kk * 16 + lr;
                const int col  = warpN * 64 + np * 16 + lc8;
                ldsm_x4_t(r4, bB + (uint32_t)(krow * BS_STRIDE_B + col * 2));
                bf[np*2][0]   = r4[0]; bf[np*2][1]   = r4[1];
                bf[np*2+1][0] = r4[2]; bf[np*2+1][1] = r4[3];
            }
            #pragma unroll
            for (int mi = 0; mi < 4; mi++)
                #pragma unroll
                for (int ni = 0; ni < 8; ni++)
                    mma_f16(acc[mi][ni], af[mi], bf[ni]);
        }
    };

    const int nch = K / 64;
    FILL(0);
    FILL(1);
    for (int c = 0; c < nch; c++) {
        if (c == nch - 1) cp_wait<0>(); else cp_wait<1>();
        __syncthreads();
        if (c + 2 < nch) FILL(c + 2);
        COMPUTE(c % 3);
    }

    #pragma unroll
    for (int mi = 0; mi < 4; mi++) {
        #pragma unroll
        for (int ni = 0; ni < 8; ni++) {
            const int gr = mBase + warpM * 64 + mi * 16 + (lane >> 2);
            const int gc = nBase + warpN * 64 + ni * 8 + (lane & 3) * 2;
            float v0 = acc[mi][ni][0], v1 = acc[mi][ni][1];
            float v2 = acc[mi][ni][2], v3 = acc[mi][ni][3];
            if (MODE != 0) {
                const float b0 = bias[gc], b1 = bias[gc + 1];
                v0 += b0; v1 += b1; v2 += b0; v3 += b1;
            }
            if (MODE == 1) {
                const float* r0p = R + (size_t)gr * Nw + gc;
                const float* r1p = R + (size_t)(gr + 8) * Nw + gc;
                v0 += r0p[0]; v1 += r0p[1]; v2 += r1p[0]; v3 += r1p[1];
            }
            if constexpr (MODE != 1) {
                __half* C = (__half*)Cv;
                if (MODE == 2) {
                    v0 = fmaxf(v0, 0.f); v1 = fmaxf(v1, 0.f);
                    v2 = fmaxf(v2, 0.f); v3 = fmaxf(v3, 0.f);
                }
                *(__half2*)(C + (size_t)gr * Nw + gc)       = __floats2half2_rn(v0, v1);
                *(__half2*)(C + (size_t)(gr + 8) * Nw + gc) = __floats2half2_rn(v2, v3);
            } else {
                float* C = (float*)Cv;
                *(float2*)(C + (size_t)gr * Nw + gc)       = make_float2(v0, v1);
                *(float2*)(C + (size_t)(gr + 8) * Nw + gc) = make_float2(v2, v3);
            }
        }
    }
}

// ---------------- Tensor-core flash attention (causal, scale 1/32) -----------
// 128 query rows / block, 4 warps; KV tiles of 64 in a 4-slot ring, 3 in
// flight, single __syncthreads per tile.
#define KS_STRIDE 144                 // bytes per row (64 halves + 8 pad)
#define Q_SMEM_B  (128 * KS_STRIDE)   // 18432
#define KV_TILE_B (64 * KS_STRIDE)    // 9216
#define ATT_SMEM  (Q_SMEM_B + 8 * KV_TILE_B)   // 92160

__global__ __launch_bounds__(128) void attn_kernel(
    const __half* __restrict__ Q, const __half* __restrict__ K,
    const __half* __restrict__ V, __half* __restrict__ O)
{
    extern __shared__ __align__(128) char smc[];
    const uint32_t smBase = smem_u32(smc);

    const int tid = threadIdx.x;
    const int wid = tid >> 5, lane = tid & 31;
    const int qt = blockIdx.x, hh = blockIdx.y, bb = blockIdx.z;
    const int qb = qt * 128;
    const size_t base = (size_t)bb * TT * DM + (size_t)hh * HS;

    const int lr  = (lane & 7) + ((lane >> 3) & 1) * 8;
    const int lc8 = (lane >> 4) * 8;

    // ---- fill Q (128 rows); committed with KV tile 0 as group 0 ----
    #pragma unroll
    for (int i = 0; i < 8; i++) {
        const int idx = i * 128 + tid;
        const int r = idx >> 3, c = idx & 7;
        cp16(smBase + (uint32_t)(r * KS_STRIDE + c * 16),
             Q + base + (size_t)(qb + r) * DM + c * 8);
    }
    auto FILLKV = [&](int kt) {
        const int s = kt & 3;
        const uint32_t kB = smBase + Q_SMEM_B + (uint32_t)(s * KV_TILE_B);
        const uint32_t vB = smBase + Q_SMEM_B + (uint32_t)((4 + s) * KV_TILE_B);
        #pragma unroll
        for (int i = 0; i < 4; i++) {
            const int idx = i * 128 + tid;
            const int r = idx >> 3, c = idx & 7;
            const size_t g = base + (size_t)(kt * 64 + r) * DM + c * 8;
            cp16(kB + (uint32_t)(r * KS_STRIDE + c * 16), K + g);
            cp16(vB + (uint32_t)(r * KS_STRIDE + c * 16), V + g);
        }
        cp_commit();
    };
    const int ntiles = 2 * qt + 2;
    FILLKV(0);              // group 0: Q + KV0
    FILLKV(1);              // group 1
    FILLKV(2);              // group 2 (always in-bounds: rows < 192 <= TT)

    uint32_t qa[2][4][4];
    float oacc[2][8][4];
    float mrow[2][2], lrow[2][2];
    #pragma unroll
    for (int mi = 0; mi < 2; mi++) {
        mrow[mi][0] = mrow[mi][1] = -1e30f;
        lrow[mi][0] = lrow[mi][1] = 0.f;
        #pragma unroll
        for (int ni = 0; ni < 8; ni++)
            #pragma unroll
            for (int t = 0; t < 4; t++) oacc[mi][ni][t] = 0.f;
    }

    for (int kt = 0; kt < ntiles; kt++) {
        if (kt + 2 < ntiles)      cp_wait<2>();
        else if (kt + 1 < ntiles) cp_wait<1>();
        else                      cp_wait<0>();
        __syncthreads();
        if (kt + 3 < ntiles) FILLKV(kt + 3);   // slot (kt-1)&3: readers synced
        if (kt == 0) {
            #pragma unroll
            for (int mi = 0; mi < 2; mi++)
                #pragma unroll
                for (int kk = 0; kk < 4; kk++) {
                    const int row = wid * 32 + mi * 16 + lr;
                    ldsm_x4(qa[mi][kk],
                            smBase + (uint32_t)(row * KS_STRIDE + (kk * 16 + lc8) * 2));
                }
        }
        const int s = kt & 3;
        const uint32_t kB = smBase + Q_SMEM_B + (uint32_t)(s * KV_TILE_B);
        const uint32_t vB = smBase + Q_SMEM_B + (uint32_t)((4 + s) * KV_TILE_B);

        // ---- S = Q @ K^T ----
        float sacc[2][8][4];
        #pragma unroll
        for (int mi = 0; mi < 2; mi++)
            #pragma unroll
            for (int ni = 0; ni < 8; ni++)
                #pragma unroll
                for (int t = 0; t < 4; t++) sacc[mi][ni][t] = 0.f;
        #pragma unroll
        for (int kk = 0; kk < 4; kk++) {
            uint32_t kb[8][2];
            #pragma unroll
            for (int ng = 0; ng < 4; ng++) {
                uint32_t r4[4];
                ldsm_x4(r4, kB + (uint32_t)((ng * 16 + lr) * KS_STRIDE + (kk * 16 + lc8) * 2));
                kb[ng*2][0]   = r4[0]; kb[ng*2][1]   = r4[2];
                kb[ng*2+1][0] = r4[1]; kb[ng*2+1][1] = r4[3];
            }
            #pragma unroll
            for (int mi = 0; mi < 2; mi++)
                #pragma unroll
                for (int ni = 0; ni < 8; ni++)
                    mma_f16(sacc[mi][ni], qa[mi][kk], kb[ni]);
        }

        // ---- online softmax in fragments ----
        const bool doMask = (kt >= 2 * qt);
        uint32_t pa[2][4][4];
        #pragma unroll
        for (int mi = 0; mi < 2; mi++) {
            const int row0 = qb + wid * 32 + mi * 16 + (lane >> 2);
            const int row1 = row0 + 8;
            float mx0 = -1e30f, mx1 = -1e30f;
            #pragma unroll
            for (int ni = 0; ni < 8; ni++) {
                const int c0 = kt * 64 + ni * 8 + (lane & 3) * 2;
                float s0 = sacc[mi][ni][0] * 0.03125f;
                float s1 = sacc[mi][ni][1] * 0.03125f;
                float s2 = sacc[mi][ni][2] * 0.03125f;
                float s3 = sacc[mi][ni][3] * 0.03125f;
                if (doMask) {
                    if (c0     > row0) s0 = -1e30f;
                    if (c0 + 1 > row0) s1 = -1e30f;
                    if (c0     > row1) s2 = -1e30f;
                    if (c0 + 1 > row1) s3 = -1e30f;
                }
                sacc[mi][ni][0] = s0; sacc[mi][ni][1] = s1;
                sacc[mi][ni][2] = s2; sacc[mi][ni][3] = s3;
                mx0 = fmaxf(mx0, fmaxf(s0, s1));
                mx1 = fmaxf(mx1, fmaxf(s2, s3));
            }
            #pragma unroll
            for (int off = 1; off <= 2; off <<= 1) {
                mx0 = fmaxf(mx0, __shfl_xor_sync(0xffffffffu, mx0, off));
                mx1 = fmaxf(mx1, __shfl_xor_sync(0xffffffffu, mx1, off));
            }
            const float mn0 = fmaxf(mrow[mi][0], mx0);
            const float mn1 = fmaxf(mrow[mi][1], mx1);
            const float cor0 = __expf(mrow[mi][0] - mn0);
            const float cor1 = __expf(mrow[mi][1] - mn1);
            mrow[mi][0] = mn0; mrow[mi][1] = mn1;
            float sum0 = 0.f, sum1 = 0.f;
            float p[8][4];
            #pragma unroll
            for (int ni = 0; ni < 8; ni++) {
                p[ni][0] = __expf(sacc[mi][ni][0] - mn0);
                p[ni][1] = __expf(sacc[mi][ni][1] - mn0);
                p[ni][2] = __expf(sacc[mi][ni][2] - mn1);
                p[ni][3] = __expf(sacc[mi][ni][3] - mn1);
                sum0 += p[ni][0] + p[ni][1];
                sum1 += p[ni][2] + p[ni][3];
            }
            lrow[mi][0] = lrow[mi][0] * cor0 + sum0;
            lrow[mi][1] = lrow[mi][1] * cor1 + sum1;
            #pragma unroll
            for (int ni = 0; ni < 8; ni++) {
                oacc[mi][ni][0] *= cor0; oacc[mi][ni][1] *= cor0;
                oacc[mi][ni][2] *= cor1; oacc[mi][ni][3] *= cor1;
            }
            #pragma unroll
            for (int jk = 0; jk < 4; jk++) {
                __half2 h0 = __floats2half2_rn(p[2*jk][0],   p[2*jk][1]);
                __half2 h1 = __floats2half2_rn(p[2*jk][2],   p[2*jk][3]);
                __half2 h2 = __floats2half2_rn(p[2*jk+1][0], p[2*jk+1][1]);
                __half2 h3 = __floats2half2_rn(p[2*jk+1][2], p[2*jk+1][3]);
                pa[mi][jk][0] = *(uint32_t*)&h0;
                pa[mi][jk][1] = *(uint32_t*)&h1;
                pa[mi][jk][2] = *(uint32_t*)&h2;
                pa[mi][jk][3] = *(uint32_t*)&h3;
            }
        }

        // ---- O += P @ V ----
        #pragma unroll
        for (int jk = 0; jk < 4; jk++) {
            uint32_t vb[8][2];
            #pragma unroll
            for (int ng = 0; ng < 4; ng++) {
                uint32_t r4[4];
                ldsm_x4_t(r4, vB + (uint32_t)((jk * 16 + lr) * KS_STRIDE + (ng * 16 + lc8) * 2));
                vb[ng*2][0]   = r4[0]; vb[ng*2][1]   = r4[1];
                vb[ng*2+1][0] = r4[2]; vb[ng*2+1][1] = r4[3];
            }
            #pragma unroll
            for (int mi = 0; mi < 2; mi++)
                #pragma unroll
                for (int ni = 0; ni < 8; ni++)
                    mma_f16(oacc[mi][ni], pa[mi][jk], vb[ni]);
        }
    }

    // ---- epilogue: normalize and store fp16 ----
    #pragma unroll
    for (int mi = 0; mi < 2; mi++) {
        float l0 = lrow[mi][0], l1 = lrow[mi][1];
        #pragma unroll
        for (int off = 1; off <= 2; off <<= 1) {
            l0 += __shfl_xor_sync(0xffffffffu, l0, off);
            l1 += __shfl_xor_sync(0xffffffffu, l1, off);
        }
        const float inv0 = 1.f / l0, inv1 = 1.f / l1;
        const int gr0 = qb + wid * 32 + mi * 16 + (lane >> 2);
        #pragma unroll
        for (int ni = 0; ni < 8; ni++) {
            const int gc = ni * 8 + (lane & 3) * 2;
            *(__half2*)(O + base + (size_t)gr0 * DM + gc) =
                __floats2half2_rn(oacc[mi][ni][0] * inv0, oacc[mi][ni][1] * inv0);
            *(__half2*)(O + base + (size_t)(gr0 + 8) * DM + gc) =
                __floats2half2_rn(oacc[mi][ni][2] * inv1, oacc[mi][ni][3] * inv1);
        }
    }
}

// ---------------- launch ----------------------------------------------------
extern "C" void kernel_launch(void* const* d_in, const int* in_sizes, int n_in,
                              void* d_out, int out_size)
{
    const float* x    = (const float*)d_in[0];
    const float* Wq   = (const float*)d_in[1];
    const float* Wk   = (const float*)d_in[2];
    const float* Wv   = (const float*)d_in[3];
    const float* Wo   = (const float*)d_in[4];
    const float* bo   = (const float*)d_in[5];
    const float* W1   = (const float*)d_in[6];
    const float* b1   = (const float*)d_in[7];
    const float* W2   = (const float*)d_in[8];
    const float* b2   = (const float*)d_in[9];
    const float* ln1g = (const float*)d_in[10];
    const float* ln1b = (const float*)d_in[11];
    const float* ln2g = (const float*)d_in[12];
    const float* ln2b = (const float*)d_in[13];
    float* out = (float*)d_out;

    __half *h, *q, *k, *v, *att, *mid, *hwq, *hwk, *hwv, *hwo, *hw1, *hw2;
    float *x1;
    cudaGetSymbolAddress((void**)&h,   g_h);
    cudaGetSymbolAddress((void**)&q,   g_q);
    cudaGetSymbolAddress((void**)&k,   g_k);
    cudaGetSymbolAddress((void**)&v,   g_v);
    cudaGetSymbolAddress((void**)&att, g_att);
    cudaGetSymbolAddress((void**)&x1,  g_x1);
    cudaGetSymbolAddress((void**)&mid, g_mid);
    cudaGetSymbolAddress((void**)&hwq, g_hwq);
    cudaGetSymbolAddress((void**)&hwk, g_hwk);
    cudaGetSymbolAddress((void**)&hwv, g_hwv);
    cudaGetSymbolAddress((void**)&hwo, g_hwo);
    cudaGetSymbolAddress((void**)&hw1, g_hw1);
    cudaGetSymbolAddress((void**)&hw2, g_hw2);

    cudaFuncSetAttribute(tgemm_kernel<0>, cudaFuncAttributeMaxDynamicSharedMemorySize, SM_BYTES);
    cudaFuncSetAttribute(tgemm_kernel<1>, cudaFuncAttributeMaxDynamicSharedMemorySize, SM_BYTES);
    cudaFuncSetAttribute(tgemm_kernel<2>, cudaFuncAttributeMaxDynamicSharedMemorySize, SM_BYTES);
    cudaFuncSetAttribute(attn_kernel,     cudaFuncAttributeMaxDynamicSharedMemorySize, ATT_SMEM);

    // 0) convert all weights to fp16 in one launch
    cvt_all_kernel<<<(N4TOT + 255) / 256, 256>>>(Wq, Wk, Wv, Wo, W1, W2,
                                                 hwq, hwk, hwv, hwo, hw1, hw2);

    // 1) LN1 -> fp16
    ln_kernel<<<MM, 256>>>(x, ln1g, ln1b, h);

    // 2) fused Q,K,V projections -> fp16
    dim3 gqkv(DM / 256, MM / 128, 3);
    tgemm_kernel<0><<<gqkv, 256, SM_BYTES>>>(h, hwq, hwk, hwv, nullptr, nullptr,
                                             q, k, v, DM, DM);

    // 3) tensor-core causal flash attention -> fp16
    dim3 ga(TT / 128, NH, BB);
    attn_kernel<<<ga, 128, ATT_SMEM>>>(q, k, v, att);

    // 4) x1 = x + att @ Wo + bo  (fp32 out)
    dim3 g1(DM / 256, MM / 128, 1);
    tgemm_kernel<1><<<g1, 256, SM_BYTES>>>(att, hwo, hwo, hwo, bo, x,
                                           x1, x1, x1, DM, DM);

    // 5) LN2 -> fp16
    ln_kernel<<<MM, 256>>>(x1, ln2g, ln2b, h);

    // 6) mid = relu(h @ W1 + b1) -> fp16
    dim3 g2(DFF / 256, MM / 128, 1);
    tgemm_kernel<2><<<g2, 256, SM_BYTES>>>(h, hw1, hw1, hw1, b1, nullptr,
                                           mid, mid, mid, DM, DFF);

    // 7) out = x1 + mid @ W2 + b2  (fp32 out)
    tgemm_kernel<1><<<g1, 256, SM_BYTES>>>(mid, hw2, hw2, hw2, b2, x1,
                                           out, out, out, DFF, DM);
}

// round 16
// speedup vs baseline: 1.0349x; 1.0064x over previous
#include <cuda_runtime.h>
#include <cuda_fp16.h>
#include <math.h>
#include <stdint.h>

// Problem constants
#define BB   8
#define TT   1024
#define DM   1024
#define NH   16
#define HS   64
#define MM   (BB*TT)          // 8192 rows
#define DFF  (4*DM)           // 4096

// ---------------- scratch (device globals; no allocation allowed) ------------
__device__ __half g_h  [MM*DM];                 // LN outputs (fp16)
__device__ __half g_q  [MM*DM];
__device__ __half g_k  [MM*DM];
__device__ __half g_v  [MM*DM];
__device__ __half g_att[MM*DM];                 // attention output (fp16)
__device__ float  g_x1 [MM*DM];
__device__ __half g_mid[(size_t)MM*DFF];        // MLP mid (fp16)
// fp16 weight copies (layout unchanged: [K,N] row-major)
__device__ __half g_hwq[DM*DM];
__device__ __half g_hwk[DM*DM];
__device__ __half g_hwv[DM*DM];
__device__ __half g_hwo[DM*DM];
__device__ __half g_hw1[(size_t)DM*DFF];
__device__ __half g_hw2[(size_t)DFF*DM];

// ---------------- helpers ----------------------------------------------------
__device__ __forceinline__ uint32_t smem_u32(const void* p) {
    uint32_t a;
    asm("{ .reg .u64 t; cvta.to.shared.u64 t, %1; cvt.u32.u64 %0, t; }" : "=r"(a) : "l"(p));
    return a;
}
__device__ __forceinline__ void cp16(uint32_t dst, const void* src) {
    asm volatile("cp.async.cg.shared.global [%0], [%1], 16;" :: "r"(dst), "l"(src));
}
__device__ __forceinline__ void cp_commit() {
    asm volatile("cp.async.commit_group;" ::: "memory");
}
template<int N>
__device__ __forceinline__ void cp_wait() {
    asm volatile("cp.async.wait_group %0;" :: "n"(N) : "memory");
}
__device__ __forceinline__ void ldsm_x4(uint32_t* r, uint32_t addr) {
    asm volatile("ldmatrix.sync.aligned.m8n8.x4.shared.b16 {%0,%1,%2,%3}, [%4];"
        : "=r"(r[0]), "=r"(r[1]), "=r"(r[2]), "=r"(r[3]) : "r"(addr));
}
__device__ __forceinline__ void ldsm_x4_t(uint32_t* r, uint32_t addr) {
    asm volatile("ldmatrix.sync.aligned.m8n8.x4.trans.shared.b16 {%0,%1,%2,%3}, [%4];"
        : "=r"(r[0]), "=r"(r[1]), "=r"(r[2]), "=r"(r[3]) : "r"(addr));
}
__device__ __forceinline__ void mma_f16(float* d, const uint32_t* a, const uint32_t* b) {
    asm volatile(
        "mma.sync.aligned.m16n8k16.row.col.f32.f16.f16.f32 "
        "{%0,%1,%2,%3}, {%4,%5,%6,%7}, {%8,%9}, {%0,%1,%2,%3};"
        : "+f"(d[0]), "+f"(d[1]), "+f"(d[2]), "+f"(d[3])
        : "r"(a[0]), "r"(a[1]), "r"(a[2]), "r"(a[3]), "r"(b[0]), "r"(b[1]));
}

// GEMM smem geometry (bytes). K-chunk = 64 halves. 3-stage pipeline.
#define AS_STRIDE_B 144
#define BS_STRIDE_B 528
#define A_STAGE_B   (128 * AS_STRIDE_B)
#define B_STAGE_B   (64  * BS_STRIDE_B)
#define STAGE_B     (A_STAGE_B + B_STAGE_B)     // 52224
#define SM_BYTES    (3 * STAGE_B)               // 156672

// ---------------- LayerNorm body (fp32 in -> fp16 out) -----------------------
__device__ __forceinline__ void ln_body(
    int row, int tid,
    const float* __restrict__ x, const float* __restrict__ g,
    const float* __restrict__ b, __half* __restrict__ out,
    float* ss, float* ssq)
{
    const float4* xr = (const float4*)(x + (size_t)row * DM);
    float4 v = xr[tid];
    float s  = v.x + v.y + v.z + v.w;
    float sq = v.x*v.x + v.y*v.y + v.z*v.z + v.w*v.w;
    #pragma unroll
    for (int off = 16; off; off >>= 1) {
        s  += __shfl_xor_sync(0xffffffffu, s,  off);
        sq += __shfl_xor_sync(0xffffffffu, sq, off);
    }
    const int w = tid >> 5, lane = tid & 31;
    if (lane == 0) { ss[w] = s; ssq[w] = sq; }
    __syncthreads();
    float tot = 0.f, totq = 0.f;
    #pragma unroll
    for (int i = 0; i < 8; i++) { tot += ss[i]; totq += ssq[i]; }
    const float mean = tot * (1.f / DM);
    const float var  = totq * (1.f / DM) - mean * mean;
    const float inv  = rsqrtf(var + 1e-5f);
    float4 gg = ((const float4*)g)[tid];
    float4 bb = ((const float4*)b)[tid];
    __half2* orow = (__half2*)(out + (size_t)row * DM);
    orow[tid*2]   = __floats2half2_rn((v.x-mean)*inv*gg.x + bb.x, (v.y-mean)*inv*gg.y + bb.y);
    orow[tid*2+1] = __floats2half2_rn((v.z-mean)*inv*gg.z + bb.z, (v.w-mean)*inv*gg.w + bb.w);
}

__global__ __launch_bounds__(256) void ln_kernel(
    const float* __restrict__ x, const float* __restrict__ g,
    const float* __restrict__ b, __half* __restrict__ out)
{
    __shared__ float ss[8], ssq[8];
    ln_body(blockIdx.x, threadIdx.x, x, g, b, out, ss, ssq);
}

// ---------------- fused: LN1 + all-weight fp32->fp16 convert -----------------
#define N4D 262144
#define N4F 1048576
#define N4TOT (4*N4D + 2*N4F)   // 3145728
#define CVT_BLOCKS ((N4TOT + 255) / 256)
__global__ __launch_bounds__(256) void cvt_ln_kernel(
    const float* __restrict__ x, const float* __restrict__ ln1g,
    const float* __restrict__ ln1b, __half* __restrict__ h,
    const float* __restrict__ Wq, const float* __restrict__ Wk,
    const float* __restrict__ Wv, const float* __restrict__ Wo,
    const float* __restrict__ W1, const float* __restrict__ W2,
    __half* __restrict__ hwq, __half* __restrict__ hwk,
    __half* __restrict__ hwv, __half* __restrict__ hwo,
    __half* __restrict__ hw1, __half* __restrict__ hw2)
{
    __shared__ float ss[8], ssq[8];
    if (blockIdx.x < MM) {
        ln_body(blockIdx.x, threadIdx.x, x, ln1g, ln1b, h, ss, ssq);
        return;
    }
    int i = (blockIdx.x - MM) * 256 + threadIdx.x;
    if (i >= N4TOT) return;
    const float* src; __half* dst; int off;
    if      (i < 1*N4D)          { src = Wq; dst = hwq; off = i; }
    else if (i < 2*N4D)          { src = Wk; dst = hwk; off = i - 1*N4D; }
    else if (i < 3*N4D)          { src = Wv; dst = hwv; off = i - 2*N4D; }
    else if (i < 4*N4D)          { src = Wo; dst = hwo; off = i - 3*N4D; }
    else if (i < 4*N4D + N4F)    { src = W1; dst = hw1; off = i - 4*N4D; }
    else                         { src = W2; dst = hw2; off = i - 4*N4D - N4F; }
    float4 v = ((const float4*)src)[off];
    ((__half2*)dst)[2*off]   = __floats2half2_rn(v.x, v.y);
    ((__half2*)dst)[2*off+1] = __floats2half2_rn(v.z, v.w);
}

// ---------------- fp16 tensor GEMM, 128x256 tile, K-chunk 64, 3-stage --------
// Fragment double-buffering: kk+1's ldmatrix issue overlaps kk's MMAs.
// MODE 0: plain, fp16 out (z selects among 3 weight/output pairs)
// MODE 1: +bias +residual(fp32), fp32 out
// MODE 2: +bias, relu, fp16 out
template<int MODE>
__global__ __launch_bounds__(256) void tgemm_kernel(
    const __half* __restrict__ A,
    const __half* __restrict__ W0, const __half* __restrict__ W1w, const __half* __restrict__ W2w,
    const float* __restrict__ bias, const float* __restrict__ R,
    void* C0v, void* C1v, void* C2v,
    int K, int Nw)
{
    extern __shared__ __align__(128) char smc[];
    const uint32_t smBase = smem_u32(smc);

    const int tid  = threadIdx.x;
    const int wid  = tid >> 5, lane = tid & 31;
    const int warpM = wid >> 2, warpN = wid & 3;
    const int z = blockIdx.z;
    const __half* Wp = (z == 0) ? W0 : (z == 1) ? W1w : W2w;
    void* Cv = (z == 0) ? C0v : (z == 1) ? C1v : C2v;

    const int mBase = blockIdx.y * 128;
    const int nBase = blockIdx.x * 256;
    const __half* Aptr = A  + (size_t)mBase * K;
    const __half* Bptr = Wp + nBase;

    const int lr  = (lane & 7) + ((lane >> 3) & 1) * 8;
    const int lc8 = (lane >> 4) * 8;

    float acc[4][8][4];
    #pragma unroll
    for (int i = 0; i < 4; i++)
        #pragma unroll
        for (int j = 0; j < 8; j++)
            #pragma unroll
            for (int t = 0; t < 4; t++) acc[i][j][t] = 0.f;

    auto FILL = [&](int c) {
        const int k0 = c * 64;
        const uint32_t aB = smBase + (uint32_t)((c % 3) * STAGE_B);
        const uint32_t bB = aB + A_STAGE_B;
        #pragma unroll
        for (int i = 0; i < 4; i++) {
            const int idx = i * 256 + tid;
            const int r = idx >> 3, cc = idx & 7;
            cp16(aB + (uint32_t)(r * AS_STRIDE_B + cc * 16),
                 Aptr + (size_t)r * K + k0 + cc * 8);
        }
        #pragma unroll
        for (int i = 0; i < 8; i++) {
            const int idx = i * 256 + tid;
            const int r = idx >> 5, cc = idx & 31;
            cp16(bB + (uint32_t)(r * BS_STRIDE_B + cc * 16),
                 Bptr + (size_t)(k0 + r) * Nw + cc * 8);
        }
        cp_commit();
    };

    uint32_t af[2][4][4], bf[2][8][2];

    auto LDFRAG = [&](uint32_t aB, uint32_t bB, int kk, int pb) {
        #pragma unroll
        for (int mi = 0; mi < 4; mi++) {
            const int row = warpM * 64 + mi * 16 + lr;
            ldsm_x4(af[pb][mi], aB + (uint32_t)(row * AS_STRIDE_B + (kk * 16 + lc8) * 2));
        }
        #pragma unroll
        for (int np = 0; np < 4; np++) {
            uint32_t r4[4];
            const int krow = kk * 16 + lr;
            const int col  = warpN * 64 + np * 16 + lc8;
            ldsm_x4_t(r4, bB + (uint32_t)(krow * BS_STRIDE_B + col * 2));
            bf[pb][np*2][0]   = r4[0]; bf[pb][np*2][1]   = r4[1];
            bf[pb][np*2+1][0] = r4[2]; bf[pb][np*2+1][1] = r4[3];
        }
    };

    auto COMPUTE = [&](int buf) {
        const uint32_t aB = smBase + (uint32_t)(buf * STAGE_B);
        const uint32_t bB = aB + A_STAGE_B;
        LDFRAG(aB, bB, 0, 0);
        #pragma unroll
        for (int kk = 0; kk < 4; kk++) {
            if (kk < 3) LDFRAG(aB, bB, kk + 1, (kk + 1) & 1);
            const int pb = kk & 1;
            #pragma unroll
            for (int mi = 0; mi < 4; mi++)
                #pragma unroll
                for (int ni = 0; ni < 8; ni++)
                    mma_f16(acc[mi][ni], af[pb][mi], bf[pb][ni]);
        }
    };

    const int nch = K / 64;
    FILL(0);
    FILL(1);
    for (int c = 0; c < nch; c++) {
        if (c == nch - 1) cp_wait<0>(); else cp_wait<1>();
        __syncthreads();
        if (c + 2 < nch) FILL(c + 2);
        COMPUTE(c % 3);
    }

    #pragma unroll
    for (int mi = 0; mi < 4; mi++) {
        #pragma unroll
        for (int ni = 0; ni < 8; ni++) {
            const int gr = mBase + warpM * 64 + mi * 16 + (lane >> 2);
            const int gc = nBase + warpN * 64 + ni * 8 + (lane & 3) * 2;
            float v0 = acc[mi][ni][0], v1 = acc[mi][ni][1];
            float v2 = acc[mi][ni][2], v3 = acc[mi][ni][3];
            if (MODE != 0) {
                const float b0 = bias[gc], b1 = bias[gc + 1];
                v0 += b0; v1 += b1; v2 += b0; v3 += b1;
            }
            if (MODE == 1) {
                const float* r0p = R + (size_t)gr * Nw + gc;
                const float* r1p = R + (size_t)(gr + 8) * Nw + gc;
                v0 += r0p[0]; v1 += r0p[1]; v2 += r1p[0]; v3 += r1p[1];
            }
            if constexpr (MODE != 1) {
                __half* C = (__half*)Cv;
                if (MODE == 2) {
                    v0 = fmaxf(v0, 0.f); v1 = fmaxf(v1, 0.f);
                    v2 = fmaxf(v2, 0.f); v3 = fmaxf(v3, 0.f);
                }
                *(__half2*)(C + (size_t)gr * Nw + gc)       = __floats2half2_rn(v0, v1);
                *(__half2*)(C + (size_t)(gr + 8) * Nw + gc) = __floats2half2_rn(v2, v3);
            } else {
                float* C = (float*)Cv;
                *(float2*)(C + (size_t)gr * Nw + gc)       = make_float2(v0, v1);
                *(float2*)(C + (size_t)(gr + 8) * Nw + gc) = make_float2(v2, v3);
            }
        }
    }
}

// ---------------- Tensor-core flash attention (causal) -----------------------
// Softmax in log2 domain: scale = (1/32)*log2(e) folded into one constant;
// exp2f replaces expf (saves the internal log2e multiply per element).
#define KS_STRIDE 144                 // bytes per row (64 halves + 8 pad)
#define Q_SMEM_B  (128 * KS_STRIDE)   // 18432
#define KV_TILE_B (64 * KS_STRIDE)    // 9216
#define ATT_SMEM  (Q_SMEM_B + 8 * KV_TILE_B)   // 92160
#define SCALE_LOG2 0.04508422f        // 0.03125 * log2(e)

__global__ __launch_bounds__(128) void attn_kernel(
    const __half* __restrict__ Q, const __half* __restrict__ K,
    const __half* __restrict__ V, __half* __restrict__ O)
{
    extern __shared__ __align__(128) char smc[];
    const uint32_t smBase = smem_u32(smc);

    const int tid = threadIdx.x;
    const int wid = tid >> 5, lane = tid & 31;
    const int qt = blockIdx.x, hh = blockIdx.y, bb = blockIdx.z;
    const int qb = qt * 128;
    const size_t base = (size_t)bb * TT * DM + (size_t)hh * HS;

    const int lr  = (lane & 7) + ((lane >> 3) & 1) * 8;
    const int lc8 = (lane >> 4) * 8;

    // ---- fill Q (128 rows); committed with KV tile 0 as group 0 ----
    #pragma unroll
    for (int i = 0; i < 8; i++) {
        const int idx = i * 128 + tid;
        const int r = idx >> 3, c = idx & 7;
        cp16(smBase + (uint32_t)(r * KS_STRIDE + c * 16),
             Q + base + (size_t)(qb + r) * DM + c * 8);
    }
    auto FILLKV = [&](int kt) {
        const int s = kt & 3;
        const uint32_t kB = smBase + Q_SMEM_B + (uint32_t)(s * KV_TILE_B);
        const uint32_t vB = smBase + Q_SMEM_B + (uint32_t)((4 + s) * KV_TILE_B);
        #pragma unroll
        for (int i = 0; i < 4; i++) {
            const int idx = i * 128 + tid;
            const int r = idx >> 3, c = idx & 7;
            const size_t g = base + (size_t)(kt * 64 + r) * DM + c * 8;
            cp16(kB + (uint32_t)(r * KS_STRIDE + c * 16), K + g);
            cp16(vB + (uint32_t)(r * KS_STRIDE + c * 16), V + g);
        }
        cp_commit();
    };
    const int ntiles = 2 * qt + 2;
    FILLKV(0);              // group 0: Q + KV0
    FILLKV(1);              // group 1
    FILLKV(2);              // group 2 (always in-bounds: rows < 192 <= TT)

    uint32_t qa[2][4][4];
    float oacc[2][8][4];
    float mrow[2][2], lrow[2][2];
    #pragma unroll
    for (int mi = 0; mi < 2; mi++) {
        mrow[mi][0] = mrow[mi][1] = -1e30f;
        lrow[mi][0] = lrow[mi][1] = 0.f;
        #pragma unroll
        for (int ni = 0; ni < 8; ni++)
            #pragma unroll
            for (int t = 0; t < 4; t++) oacc[mi][ni][t] = 0.f;
    }

    for (int kt = 0; kt < ntiles; kt++) {
        if (kt + 2 < ntiles)      cp_wait<2>();
        else if (kt + 1 < ntiles) cp_wait<1>();
        else                      cp_wait<0>();
        __syncthreads();
        if (kt + 3 < ntiles) FILLKV(kt + 3);   // slot (kt-1)&3: readers synced
        if (kt == 0) {
            #pragma unroll
            for (int mi = 0; mi < 2; mi++)
                #pragma unroll
                for (int kk = 0; kk < 4; kk++) {
                    const int row = wid * 32 + mi * 16 + lr;
                    ldsm_x4(qa[mi][kk],
                            smBase + (uint32_t)(row * KS_STRIDE + (kk * 16 + lc8) * 2));
                }
        }
        const int s = kt & 3;
        const uint32_t kB = smBase + Q_SMEM_B + (uint32_t)(s * KV_TILE_B);
        const uint32_t vB = smBase + Q_SMEM_B + (uint32_t)((4 + s) * KV_TILE_B);

        // ---- S = Q @ K^T ----
        float sacc[2][8][4];
        #pragma unroll
        for (int mi = 0; mi < 2; mi++)
            #pragma unroll
            for (int ni = 0; ni < 8; ni++)
                #pragma unroll
                for (int t = 0; t < 4; t++) sacc[mi][ni][t] = 0.f;
        #pragma unroll
        for (int kk = 0; kk < 4; kk++) {
            uint32_t kb[8][2];
            #pragma unroll
            for (int ng = 0; ng < 4; ng++) {
                uint32_t r4[4];
                ldsm_x4(r4, kB + (uint32_t)((ng * 16 + lr) * KS_STRIDE + (kk * 16 + lc8) * 2));
                kb[ng*2][0]   = r4[0]; kb[ng*2][1]   = r4[2];
                kb[ng*2+1][0] = r4[1]; kb[ng*2+1][1] = r4[3];
            }
            #pragma unroll
            for (int mi = 0; mi < 2; mi++)
                #pragma unroll
                for (int ni = 0; ni < 8; ni++)
                    mma_f16(sacc[mi][ni], qa[mi][kk], kb[ni]);
        }

        // ---- online softmax (log2 domain) ----
        const bool doMask = (kt >= 2 * qt);
        uint32_t pa[2][4][4];
        #pragma unroll
        for (int mi = 0; mi < 2; mi++) {
            const int row0 = qb + wid * 32 + mi * 16 + (lane >> 2);
            const int row1 = row0 + 8;
            float mx0 = -1e30f, mx1 = -1e30f;
            #pragma unroll
            for (int ni = 0; ni < 8; ni++) {
                const int c0 = kt * 64 + ni * 8 + (lane & 3) * 2;
                float s0 = sacc[mi][ni][0] * SCALE_LOG2;
                float s1 = sacc[mi][ni][1] * SCALE_LOG2;
                float s2 = sacc[mi][ni][2] * SCALE_LOG2;
                float s3 = sacc[mi][ni][3] * SCALE_LOG2;
                if (doMask) {
                    if (c0     > row0) s0 = -1e30f;
                    if (c0 + 1 > row0) s1 = -1e30f;
                    if (c0     > row1) s2 = -1e30f;
                    if (c0 + 1 > row1) s3 = -1e30f;
                }
                sacc[mi][ni][0] = s0; sacc[mi][ni][1] = s1;
                sacc[mi][ni][2] = s2; sacc[mi][ni][3] = s3;
                mx0 = fmaxf(mx0, fmaxf(s0, s1));
                mx1 = fmaxf(mx1, fmaxf(s2, s3));
            }
            #pragma unroll
            for (int off = 1; off <= 2; off <<= 1) {
                mx0 = fmaxf(mx0, __shfl_xor_sync(0xffffffffu, mx0, off));
                mx1 = fmaxf(mx1, __shfl_xor_sync(0xffffffffu, mx1, off));
            }
            const float mn0 = fmaxf(mrow[mi][0], mx0);
            const float mn1 = fmaxf(mrow[mi][1], mx1);
            const float cor0 = exp2f(mrow[mi][0] - mn0);
            const float cor1 = exp2f(mrow[mi][1] - mn1);
            mrow[mi][0] = mn0; mrow[mi][1] = mn1;
            float sum0 = 0.f, sum1 = 0.f;
            float p[8][4];
            #pragma unroll
            for (int ni = 0; ni < 8; ni++) {
                p[ni][0] = exp2f(sacc[mi][ni][0] - mn0);
                p[ni][1] = exp2f(sacc[mi][ni][1] - mn0);
                p[ni][2] = exp2f(sacc[mi][ni][2] - mn1);
                p[ni][3] = exp2f(sacc[mi][ni][3] - mn1);
                sum0 += p[ni][0] + p[ni][1];
                sum1 += p[ni][2] + p[ni][3];
            }
            lrow[mi][0] = lrow[mi][0] * cor0 + sum0;
            lrow[mi][1] = lrow[mi][1] * cor1 + sum1;
            #pragma unroll
            for (int ni = 0; ni < 8; ni++) {
                oacc[mi][ni][0] *= cor0; oacc[mi][ni][1] *= cor0;
                oacc[mi][ni][2] *= cor1; oacc[mi][ni][3] *= cor1;
            }
            #pragma unroll
            for (int jk = 0; jk < 4; jk++) {
                __half2 h0 = __floats2half2_rn(p[2*jk][0],   p[2*jk][1]);
                __half2 h1 = __floats2half2_rn(p[2*jk][2],   p[2*jk][3]);
                __half2 h2 = __floats2half2_rn(p[2*jk+1][0], p[2*jk+1][1]);
                __half2 h3 = __floats2half2_rn(p[2*jk+1][2], p[2*jk+1][3]);
                pa[mi][jk][0] = *(uint32_t*)&h0;
                pa[mi][jk][1] = *(uint32_t*)&h1;
                pa[mi][jk][2] = *(uint32_t*)&h2;
                pa[mi][jk][3] = *(uint32_t*)&h3;
            }
        }

        // ---- O += P @ V ----
        #pragma unroll
        for (int jk = 0; jk < 4; jk++) {
            uint32_t vb[8][2];
            #pragma unroll
            for (int ng = 0; ng < 4; ng++) {
                uint32_t r4[4];
                ldsm_x4_t(r4, vB + (uint32_t)((jk * 16 + lr) * KS_STRIDE + (ng * 16 + lc8) * 2));
                vb[ng*2][0]   = r4[0]; vb[ng*2][1]   = r4[1];
                vb[ng*2+1][0] = r4[2]; vb[ng*2+1][1] = r4[3];
            }
            #pragma unroll
            for (int mi = 0; mi < 2; mi++)
                #pragma unroll
                for (int ni = 0; ni < 8; ni++)
                    mma_f16(oacc[mi][ni], pa[mi][jk], vb[ni]);
        }
    }

    // ---- epilogue: normalize and store fp16 ----
    #pragma unroll
    for (int mi = 0; mi < 2; mi++) {
        float l0 = lrow[mi][0], l1 = lrow[mi][1];
        #pragma unroll
        for (int off = 1; off <= 2; off <<= 1) {
            l0 += __shfl_xor_sync(0xffffffffu, l0, off);
            l1 += __shfl_xor_sync(0xffffffffu, l1, off);
        }
        const float inv0 = 1.f / l0, inv1 = 1.f / l1;
        const int gr0 = qb + wid * 32 + mi * 16 + (lane >> 2);
        #pragma unroll
        for (int ni = 0; ni < 8; ni++) {
            const int gc = ni * 8 + (lane & 3) * 2;
            *(__half2*)(O + base + (size_t)gr0 * DM + gc) =
                __floats2half2_rn(oacc[mi][ni][0] * inv0, oacc[mi][ni][1] * inv0);
            *(__half2*)(O + base + (size_t)(gr0 + 8) * DM + gc) =
                __floats2half2_rn(oacc[mi][ni][2] * inv1, oacc[mi][ni][3] * inv1);
        }
    }
}

// ---------------- launch ----------------------------------------------------
extern "C" void kernel_launch(void* const* d_in, const int* in_sizes, int n_in,
                              void* d_out, int out_size)
{
    const float* x    = (const float*)d_in[0];
    const float* Wq   = (const float*)d_in[1];
    const float* Wk   = (const float*)d_in[2];
    const float* Wv   = (const float*)d_in[3];
    const float* Wo   = (const float*)d_in[4];
    const float* bo   = (const float*)d_in[5];
    const float* W1   = (const float*)d_in[6];
    const float* b1   = (const float*)d_in[7];
    const float* W2   = (const float*)d_in[8];
    const float* b2   = (const float*)d_in[9];
    const float* ln1g = (const float*)d_in[10];
    const float* ln1b = (const float*)d_in[11];
    const float* ln2g = (const float*)d_in[12];
    const float* ln2b = (const float*)d_in[13];
    float* out = (float*)d_out;

    __half *h, *q, *k, *v, *att, *mid, *hwq, *hwk, *hwv, *hwo, *hw1, *hw2;
    float *x1;
    cudaGetSymbolAddress((void**)&h,   g_h);
    cudaGetSymbolAddress((void**)&q,   g_q);
    cudaGetSymbolAddress((void**)&k,   g_k);
    cudaGetSymbolAddress((void**)&v,   g_v);
    cudaGetSymbolAddress((void**)&att, g_att);
    cudaGetSymbolAddress((void**)&x1,  g_x1);
    cudaGetSymbolAddress((void**)&mid, g_mid);
    cudaGetSymbolAddress((void**)&hwq, g_hwq);
    cudaGetSymbolAddress((void**)&hwk, g_hwk);
    cudaGetSymbolAddress((void**)&hwv, g_hwv);
    cudaGetSymbolAddress((void**)&hwo, g_hwo);
    cudaGetSymbolAddress((void**)&hw1, g_hw1);
    cudaGetSymbolAddress((void**)&hw2, g_hw2);

    cudaFuncSetAttribute(tgemm_kernel<0>, cudaFuncAttributeMaxDynamicSharedMemorySize, SM_BYTES);
    cudaFuncSetAttribute(tgemm_kernel<1>, cudaFuncAttributeMaxDynamicSharedMemorySize, SM_BYTES);
    cudaFuncSetAttribute(tgemm_kernel<2>, cudaFuncAttributeMaxDynamicSharedMemorySize, SM_BYTES);
    cudaFuncSetAttribute(attn_kernel,     cudaFuncAttributeMaxDynamicSharedMemorySize, ATT_SMEM);

    // 0+1) fused: LN1 -> fp16  AND  convert all weights to fp16
    cvt_ln_kernel<<<MM + CVT_BLOCKS, 256>>>(x, ln1g, ln1b, h,
                                            Wq, Wk, Wv, Wo, W1, W2,
                                            hwq, hwk, hwv, hwo, hw1, hw2);

    // 2) fused Q,K,V projections -> fp16
    dim3 gqkv(DM / 256, MM / 128, 3);
    tgemm_kernel<0><<<gqkv, 256, SM_BYTES>>>(h, hwq, hwk, hwv, nullptr, nullptr,
                                             q, k, v, DM, DM);

    // 3) tensor-core causal flash attention -> fp16
    dim3 ga(TT / 128, NH, BB);
    attn_kernel<<<ga, 128, ATT_SMEM>>>(q, k, v, att);

    // 4) x1 = x + att @ Wo + bo  (fp32 out)
    dim3 g1(DM / 256, MM / 128, 1);
    tgemm_kernel<1><<<g1, 256, SM_BYTES>>>(att, hwo, hwo, hwo, bo, x,
                                           x1, x1, x1, DM, DM);

    // 5) LN2 -> fp16
    ln_kernel<<<MM, 256>>>(x1, ln2g, ln2b, h);

    // 6) mid = relu(h @ W1 + b1) -> fp16
    dim3 g2(DFF / 256, MM / 128, 1);
    tgemm_kernel<2><<<g2, 256, SM_BYTES>>>(h, hw1, hw1, hw1, b1, nullptr,
                                           mid, mid, mid, DM, DFF);

    // 7) out = x1 + mid @ W2 + b2  (fp32 out)
    tgemm_kernel<1><<<g1, 256, SM_BYTES>>>(mid, hw2, hw2, hw2, b2, x1,
                                           out, out, out, DFF, DM);
}